// round 2
// baseline (speedup 1.0000x reference)
#include <cuda_runtime.h>
#include <cuda_bf16.h>

// Problem constants (fixed by the dataset)
#define N_NODES   50000
#define F_IN      256
#define F_OUT     64
#define N_EDGES   1600000
#define ALPHA     0.2f

// Scratch (static device globals; no allocation allowed)
__device__ float g_Wh[N_NODES * F_OUT];      // 12.8 MB
__device__ float g_ssrc[N_NODES];
__device__ float g_sdst[N_NODES];
__device__ int   g_count[N_NODES];
__device__ int   g_rowstart[N_NODES];
__device__ int   g_cursor[N_NODES];
__device__ int2  g_edges[N_EDGES];           // sorted-by-src (dst, w-bits), 12.8 MB

// ---------------------------------------------------------------------------
// Kernel 1: Wh = x @ W   (smem-tiled fp32 GEMM, BM=64 BN=64 BK=32) — known good
// ---------------------------------------------------------------------------
#define BM 64
#define BN 64
#define BK 32

__global__ __launch_bounds__(256) void gemm_kernel(
    const float* __restrict__ x, const float* __restrict__ W,
    float* __restrict__ Wh, int nrows)
{
    __shared__ float As[BK][BM + 1];   // stored transposed: As[k][m]
    __shared__ float Bs[BK][BN];

    const int block_row = blockIdx.x * BM;
    const int tid = threadIdx.x;
    const int tr = (tid / 16) * 4;
    const int tc = (tid % 16) * 4;

    float acc[4][4] = {};

    for (int k0 = 0; k0 < F_IN; k0 += BK) {
        #pragma unroll
        for (int i = 0; i < 2; i++) {
            int idx = tid + i * 256;
            int m   = idx >> 3;
            int kk  = (idx & 7) * 4;
            int gm  = block_row + m;
            float4 v = make_float4(0.f, 0.f, 0.f, 0.f);
            if (gm < nrows)
                v = *reinterpret_cast<const float4*>(x + (size_t)gm * F_IN + k0 + kk);
            As[kk + 0][m] = v.x;
            As[kk + 1][m] = v.y;
            As[kk + 2][m] = v.z;
            As[kk + 3][m] = v.w;
        }
        #pragma unroll
        for (int i = 0; i < 2; i++) {
            int idx = tid + i * 256;
            int kk  = idx >> 4;
            int n   = (idx & 15) * 4;
            *reinterpret_cast<float4*>(&Bs[kk][n]) =
                *reinterpret_cast<const float4*>(W + (size_t)(k0 + kk) * F_OUT + n);
        }
        __syncthreads();

        #pragma unroll
        for (int k = 0; k < BK; k++) {
            float a0 = As[k][tr + 0];
            float a1 = As[k][tr + 1];
            float a2 = As[k][tr + 2];
            float a3 = As[k][tr + 3];
            float4 b = *reinterpret_cast<float4*>(&Bs[k][tc]);
            acc[0][0] += a0 * b.x; acc[0][1] += a0 * b.y; acc[0][2] += a0 * b.z; acc[0][3] += a0 * b.w;
            acc[1][0] += a1 * b.x; acc[1][1] += a1 * b.y; acc[1][2] += a1 * b.z; acc[1][3] += a1 * b.w;
            acc[2][0] += a2 * b.x; acc[2][1] += a2 * b.y; acc[2][2] += a2 * b.z; acc[2][3] += a2 * b.w;
            acc[3][0] += a3 * b.x; acc[3][1] += a3 * b.y; acc[3][2] += a3 * b.z; acc[3][3] += a3 * b.w;
        }
        __syncthreads();
    }

    #pragma unroll
    for (int i = 0; i < 4; i++) {
        int m = block_row + tr + i;
        if (m < nrows) {
            *reinterpret_cast<float4*>(Wh + (size_t)m * F_OUT + tc) =
                make_float4(acc[i][0], acc[i][1], acc[i][2], acc[i][3]);
        }
    }
}

// ---------------------------------------------------------------------------
// Kernel 2: per-node scores (one warp per row)
// ---------------------------------------------------------------------------
__global__ __launch_bounds__(256) void score_kernel(
    const float* __restrict__ Wh, const float* __restrict__ a,
    float* __restrict__ ssrc, float* __restrict__ sdst, int nrows)
{
    int row  = blockIdx.x * 8 + (threadIdx.x >> 5);
    int lane = threadIdx.x & 31;
    if (row >= nrows) return;

    const float* wr = Wh + (size_t)row * F_OUT;
    float v0 = wr[lane], v1 = wr[lane + 32];
    float p = v0 * a[lane]      + v1 * a[lane + 32];
    float q = v0 * a[64 + lane] + v1 * a[96 + lane];
    #pragma unroll
    for (int o = 16; o; o >>= 1) {
        p += __shfl_xor_sync(0xffffffffu, p, o);
        q += __shfl_xor_sync(0xffffffffu, q, o);
    }
    if (lane == 0) { ssrc[row] = p; sdst[row] = q; }
}

// ---------------------------------------------------------------------------
// Kernel 3: zero degree counters
// ---------------------------------------------------------------------------
__global__ void zero_count_kernel(int* __restrict__ count, int nrows)
{
    int i = blockIdx.x * blockDim.x + threadIdx.x;
    if (i < nrows) count[i] = 0;
}

// ---------------------------------------------------------------------------
// Kernel 4: histogram of src
// ---------------------------------------------------------------------------
__global__ __launch_bounds__(256) void hist_kernel(
    const int* __restrict__ src, int* __restrict__ count, int nedges)
{
    int e = blockIdx.x * blockDim.x + threadIdx.x;
    if (e < nedges) atomicAdd(count + __ldg(src + e), 1);
}

// ---------------------------------------------------------------------------
// Kernel 5: single-block exclusive scan over counts (n = 50000, tiny)
// ---------------------------------------------------------------------------
__global__ __launch_bounds__(1024) void scan_kernel(
    const int* __restrict__ count, int* __restrict__ rowstart,
    int* __restrict__ cursor, int n)
{
    __shared__ int partial[1024];
    const int tid   = threadIdx.x;
    const int chunk = (n + 1023) / 1024;
    const int beg   = tid * chunk;
    const int end   = min(beg + chunk, n);

    int s = 0;
    for (int i = beg; i < end; i++) s += count[i];
    partial[tid] = s;
    __syncthreads();

    // Hillis-Steele inclusive scan over 1024 partials
    for (int off = 1; off < 1024; off <<= 1) {
        int v = (tid >= off) ? partial[tid - off] : 0;
        __syncthreads();
        partial[tid] += v;
        __syncthreads();
    }

    int ex = (tid > 0) ? partial[tid - 1] : 0;
    for (int i = beg; i < end; i++) {
        rowstart[i] = ex;
        cursor[i]   = ex;
        ex += count[i];
    }
}

// ---------------------------------------------------------------------------
// Kernel 6: scatter — compute edge weight, place (dst, w) into src-sorted slot
// ---------------------------------------------------------------------------
__global__ __launch_bounds__(256) void scatter_kernel(
    const int* __restrict__ src, const int* __restrict__ dst,
    const float* __restrict__ ssrc, const float* __restrict__ sdst,
    int* __restrict__ cursor, int2* __restrict__ edges, int nedges)
{
    int e = blockIdx.x * blockDim.x + threadIdx.x;
    if (e >= nedges) return;

    int s = __ldg(src + e);
    int d = __ldg(dst + e);
    float score = __ldg(ssrc + s) + __ldg(sdst + d);
    float l = score > 0.f ? score : ALPHA * score;
    float w = __expf(-l);

    int pos = atomicAdd(cursor + s, 1);
    edges[pos] = make_int2(d, __float_as_int(w));
}

// ---------------------------------------------------------------------------
// Kernel 7: warp-per-node aggregation + divide + ELU, fused to output.
// Each lane owns 2 output features (float2). One LDG.64 per edge per warp.
// ---------------------------------------------------------------------------
__global__ __launch_bounds__(256) void aggregate_kernel(
    const int2* __restrict__ edges, const int* __restrict__ rowstart,
    const int* __restrict__ count, const float* __restrict__ Wh,
    float* __restrict__ out, int nrows)
{
    int node = blockIdx.x * 8 + (threadIdx.x >> 5);
    int lane = threadIdx.x & 31;
    if (node >= nrows) return;

    const int start = __ldg(rowstart + node);
    const int cnt   = __ldg(count + node);
    const float2* __restrict__ Wh2 = reinterpret_cast<const float2*>(Wh);

    float accx = 0.f, accy = 0.f, wsum = 0.f;

    for (int j = 0; j < cnt; j += 32) {
        int2 ed = make_int2(0, 0);
        if (j + lane < cnt) ed = __ldg(edges + start + j + lane);
        int m = min(32, cnt - j);
        #pragma unroll 4
        for (int t = 0; t < m; t++) {
            int   d = __shfl_sync(0xffffffffu, ed.x, t);
            float w = __int_as_float(__shfl_sync(0xffffffffu, ed.y, t));
            float2 v = __ldg(Wh2 + (size_t)d * 32 + lane);
            accx += w * v.x;
            accy += w * v.y;
            wsum += w;
        }
    }

    float inv = 1.0f / wsum;
    float ox = accx * inv;
    float oy = accy * inv;
    ox = ox > 0.f ? ox : expm1f(ox);
    oy = oy > 0.f ? oy : expm1f(oy);
    reinterpret_cast<float2*>(out)[(size_t)node * 32 + lane] = make_float2(ox, oy);
}

// ---------------------------------------------------------------------------
// Launch
// ---------------------------------------------------------------------------
extern "C" void kernel_launch(void* const* d_in, const int* in_sizes, int n_in,
                              void* d_out, int out_size)
{
    const float* x    = (const float*)d_in[0];
    const int*   edge = (const int*)d_in[1];
    const float* W    = (const float*)d_in[2];
    const float* a    = (const float*)d_in[3];
    float*       out  = (float*)d_out;

    const int nrows  = in_sizes[0] / F_IN;     // 50000
    const int nedges = in_sizes[1] / 2;        // 1600000
    const int* src = edge;
    const int* dst = edge + nedges;

    float *Wh, *ssrc, *sdst;
    int *count, *rowstart, *cursor;
    int2 *edges;
    cudaGetSymbolAddress((void**)&Wh,       g_Wh);
    cudaGetSymbolAddress((void**)&ssrc,     g_ssrc);
    cudaGetSymbolAddress((void**)&sdst,     g_sdst);
    cudaGetSymbolAddress((void**)&count,    g_count);
    cudaGetSymbolAddress((void**)&rowstart, g_rowstart);
    cudaGetSymbolAddress((void**)&cursor,   g_cursor);
    cudaGetSymbolAddress((void**)&edges,    g_edges);

    // 1. GEMM
    gemm_kernel<<<(nrows + BM - 1) / BM, 256>>>(x, W, Wh, nrows);

    // 2. node scores
    score_kernel<<<(nrows + 7) / 8, 256>>>(Wh, a, ssrc, sdst, nrows);

    // 3. zero counters
    zero_count_kernel<<<(nrows + 255) / 256, 256>>>(count, nrows);

    // 4. histogram of src
    hist_kernel<<<(nedges + 255) / 256, 256>>>(src, count, nedges);

    // 5. scan -> rowstart / cursor
    scan_kernel<<<1, 1024>>>(count, rowstart, cursor, nrows);

    // 6. scatter (dst, w) into src-sorted order
    scatter_kernel<<<(nedges + 255) / 256, 256>>>(src, dst, ssrc, sdst,
                                                  cursor, edges, nedges);

    // 7. aggregate + finalize
    aggregate_kernel<<<(nrows + 7) / 8, 256>>>(edges, rowstart, count, Wh,
                                               out, nrows);
}

// round 3
// speedup vs baseline: 1.1480x; 1.1480x over previous
#include <cuda_runtime.h>
#include <cuda_fp16.h>
#include <cuda_bf16.h>

// Problem constants (fixed by the dataset)
#define N_NODES   50000
#define F_IN      256
#define F_OUT     64
#define N_EDGES   1600000
#define ALPHA     0.2f

// Scratch (static device globals; no allocation allowed)
__device__ float  g_Wh[N_NODES * F_OUT];      // 12.8 MB (fp32, for nothing else now but kept for safety of scores path)
__device__ __half g_Whh[N_NODES * F_OUT];     // 6.4 MB  (fp16 copy for edge gathers)
__device__ float  g_accum[N_NODES * F_OUT];   // 12.8 MB
__device__ float  g_ssrc[N_NODES];
__device__ float  g_sdst[N_NODES];
__device__ float  g_rowsum[N_NODES];

// ---------------------------------------------------------------------------
// Kernel 1: Wh = x @ W  + fused epilogue:
//   - write fp32 Wh (not strictly needed downstream, cheap)
//   - write fp16 Whh (edge-gather copy)
//   - compute per-row scores s_src = Wh.a[:64], s_dst = Wh.a[64:]
// BM=64 BN=64(=F_OUT) BK=32, 256 threads, 4x4 micro-tile.
// Thread group g = tid/16 owns rows tr..tr+3; 16 threads cover all 64 cols.
// ---------------------------------------------------------------------------
#define BM 64
#define BN 64
#define BK 32

__global__ __launch_bounds__(256) void gemm_kernel(
    const float* __restrict__ x, const float* __restrict__ W,
    const float* __restrict__ a,
    float* __restrict__ Wh, __half* __restrict__ Whh,
    float* __restrict__ ssrc, float* __restrict__ sdst, int nrows)
{
    __shared__ float As[BK][BM + 1];   // transposed: As[k][m]
    __shared__ float Bs[BK][BN];

    const int block_row = blockIdx.x * BM;
    const int tid = threadIdx.x;
    const int tr = (tid / 16) * 4;     // row offset of 4x4 micro-tile
    const int tc = (tid % 16) * 4;     // col offset

    float acc[4][4] = {};

    for (int k0 = 0; k0 < F_IN; k0 += BK) {
        #pragma unroll
        for (int i = 0; i < 2; i++) {
            int idx = tid + i * 256;
            int m   = idx >> 3;
            int kk  = (idx & 7) * 4;
            int gm  = block_row + m;
            float4 v = make_float4(0.f, 0.f, 0.f, 0.f);
            if (gm < nrows)
                v = *reinterpret_cast<const float4*>(x + (size_t)gm * F_IN + k0 + kk);
            As[kk + 0][m] = v.x;
            As[kk + 1][m] = v.y;
            As[kk + 2][m] = v.z;
            As[kk + 3][m] = v.w;
        }
        #pragma unroll
        for (int i = 0; i < 2; i++) {
            int idx = tid + i * 256;
            int kk  = idx >> 4;
            int n   = (idx & 15) * 4;
            *reinterpret_cast<float4*>(&Bs[kk][n]) =
                *reinterpret_cast<const float4*>(W + (size_t)(k0 + kk) * F_OUT + n);
        }
        __syncthreads();

        #pragma unroll
        for (int k = 0; k < BK; k++) {
            float a0 = As[k][tr + 0];
            float a1 = As[k][tr + 1];
            float a2 = As[k][tr + 2];
            float a3 = As[k][tr + 3];
            float4 b = *reinterpret_cast<float4*>(&Bs[k][tc]);
            acc[0][0] += a0 * b.x; acc[0][1] += a0 * b.y; acc[0][2] += a0 * b.z; acc[0][3] += a0 * b.w;
            acc[1][0] += a1 * b.x; acc[1][1] += a1 * b.y; acc[1][2] += a1 * b.z; acc[1][3] += a1 * b.w;
            acc[2][0] += a2 * b.x; acc[2][1] += a2 * b.y; acc[2][2] += a2 * b.z; acc[2][3] += a2 * b.w;
            acc[3][0] += a3 * b.x; acc[3][1] += a3 * b.y; acc[3][2] += a3 * b.z; acc[3][3] += a3 * b.w;
        }
        __syncthreads();
    }

    // attention-vector slices this thread needs
    float4 av1 = *reinterpret_cast<const float4*>(a + tc);        // a[:64]
    float4 av2 = *reinterpret_cast<const float4*>(a + 64 + tc);   // a[64:]

    #pragma unroll
    for (int i = 0; i < 4; i++) {
        int m = block_row + tr + i;
        bool valid = (m < nrows);

        if (valid) {
            *reinterpret_cast<float4*>(Wh + (size_t)m * F_OUT + tc) =
                make_float4(acc[i][0], acc[i][1], acc[i][2], acc[i][3]);
            // fp16 copy (4 halves = 8 bytes)
            __half2 h0 = __floats2half2_rn(acc[i][0], acc[i][1]);
            __half2 h1 = __floats2half2_rn(acc[i][2], acc[i][3]);
            *reinterpret_cast<__half2*>(Whh + (size_t)m * F_OUT + tc + 0) = h0;
            *reinterpret_cast<__half2*>(Whh + (size_t)m * F_OUT + tc + 2) = h1;
        }

        // row scores: reduce over the 16 threads covering this row
        float p = acc[i][0] * av1.x + acc[i][1] * av1.y + acc[i][2] * av1.z + acc[i][3] * av1.w;
        float q = acc[i][0] * av2.x + acc[i][1] * av2.y + acc[i][2] * av2.z + acc[i][3] * av2.w;
        #pragma unroll
        for (int o = 8; o; o >>= 1) {
            p += __shfl_xor_sync(0xffffffffu, p, o, 16);
            q += __shfl_xor_sync(0xffffffffu, q, o, 16);
        }
        if (valid && (tid & 15) == 0) {
            ssrc[m] = p;
            sdst[m] = q;
        }
    }
}

// ---------------------------------------------------------------------------
// Kernel 2: zero accumulators
// ---------------------------------------------------------------------------
__global__ void zero_kernel(float* __restrict__ accum, float* __restrict__ rowsum, int nrows)
{
    int i = blockIdx.x * blockDim.x + threadIdx.x;           // float4 index
    int n4 = nrows * (F_OUT / 4);
    if (i < n4)
        reinterpret_cast<float4*>(accum)[i] = make_float4(0.f, 0.f, 0.f, 0.f);
    if (i < nrows)
        rowsum[i] = 0.f;
}

// ---------------------------------------------------------------------------
// Kernel 3: edge aggregation.  8 threads per edge; each handles 8 features.
// Gather is fp16 (16 B per thread per edge), accumulate fp32 via red.v4.
// ---------------------------------------------------------------------------
__device__ __forceinline__ void red_add_v4(float* addr, float4 v)
{
    asm volatile("red.global.add.v4.f32 [%0], {%1, %2, %3, %4};"
                 :: "l"(addr), "f"(v.x), "f"(v.y), "f"(v.z), "f"(v.w)
                 : "memory");
}

__global__ __launch_bounds__(256) void edge_kernel(
    const int* __restrict__ src, const int* __restrict__ dst,
    const float* __restrict__ ssrc, const float* __restrict__ sdst,
    const __half* __restrict__ Whh,
    float* __restrict__ accum, float* __restrict__ rowsum, int nedges)
{
    int g = blockIdx.x * blockDim.x + threadIdx.x;
    int e = g >> 3;          // edge index
    int t = g & 7;           // sub-thread within edge
    if (e >= nedges) return;

    int s = __ldg(src + e);
    int d = __ldg(dst + e);

    float score = __ldg(ssrc + s) + __ldg(sdst + d);
    float l = score > 0.f ? score : ALPHA * score;
    float w = __expf(-l);

    if (t == 0)
        atomicAdd(rowsum + s, w);

    // 8 halves = 16 bytes per thread
    const uint4* wp = reinterpret_cast<const uint4*>(Whh + (size_t)d * F_OUT) + t;
    uint4 hv = __ldg(wp);

    float2 f0 = __half22float2(*reinterpret_cast<__half2*>(&hv.x));
    float2 f1 = __half22float2(*reinterpret_cast<__half2*>(&hv.y));
    float2 f2 = __half22float2(*reinterpret_cast<__half2*>(&hv.z));
    float2 f3 = __half22float2(*reinterpret_cast<__half2*>(&hv.w));

    float4 v0 = make_float4(f0.x * w, f0.y * w, f1.x * w, f1.y * w);
    float4 v1 = make_float4(f2.x * w, f2.y * w, f3.x * w, f3.y * w);

    float* ap = accum + (size_t)s * F_OUT + t * 8;
    red_add_v4(ap + 0, v0);
    red_add_v4(ap + 4, v1);
}

// ---------------------------------------------------------------------------
// Kernel 4: finalize: out = ELU(accum / rowsum)
// ---------------------------------------------------------------------------
__global__ void finalize_kernel(
    const float* __restrict__ accum, const float* __restrict__ rowsum,
    float* __restrict__ out, int nrows)
{
    int i = blockIdx.x * blockDim.x + threadIdx.x;   // float4 index
    int n4 = nrows * (F_OUT / 4);
    if (i >= n4) return;
    int row = i >> 4;                                // 16 float4 per row
    float inv = 1.0f / rowsum[row];
    float4 v = reinterpret_cast<const float4*>(accum)[i];
    v.x *= inv; v.y *= inv; v.z *= inv; v.w *= inv;
    v.x = v.x > 0.f ? v.x : expm1f(v.x);
    v.y = v.y > 0.f ? v.y : expm1f(v.y);
    v.z = v.z > 0.f ? v.z : expm1f(v.z);
    v.w = v.w > 0.f ? v.w : expm1f(v.w);
    reinterpret_cast<float4*>(out)[i] = v;
}

// ---------------------------------------------------------------------------
// Launch
// ---------------------------------------------------------------------------
extern "C" void kernel_launch(void* const* d_in, const int* in_sizes, int n_in,
                              void* d_out, int out_size)
{
    const float* x    = (const float*)d_in[0];
    const int*   edge = (const int*)d_in[1];
    const float* W    = (const float*)d_in[2];
    const float* a    = (const float*)d_in[3];
    float*       out  = (float*)d_out;

    const int nrows  = in_sizes[0] / F_IN;     // 50000
    const int nedges = in_sizes[1] / 2;        // 1600000
    const int* src = edge;
    const int* dst = edge + nedges;

    float *Wh, *accum, *ssrc, *sdst, *rowsum;
    __half *Whh;
    cudaGetSymbolAddress((void**)&Wh,     g_Wh);
    cudaGetSymbolAddress((void**)&Whh,    g_Whh);
    cudaGetSymbolAddress((void**)&accum,  g_accum);
    cudaGetSymbolAddress((void**)&ssrc,   g_ssrc);
    cudaGetSymbolAddress((void**)&sdst,   g_sdst);
    cudaGetSymbolAddress((void**)&rowsum, g_rowsum);

    // 1. GEMM + scores + fp16 copy (fused epilogue)
    gemm_kernel<<<(nrows + BM - 1) / BM, 256>>>(x, W, a, Wh, Whh, ssrc, sdst, nrows);

    // 2. zero accumulators
    int n4 = nrows * (F_OUT / 4);
    zero_kernel<<<(n4 + 255) / 256, 256>>>(accum, rowsum, nrows);

    // 3. edge aggregation (8 threads / edge, fp16 gather, fp32 red)
    long long tot = (long long)nedges * 8;
    edge_kernel<<<(int)((tot + 255) / 256), 256>>>(src, dst, ssrc, sdst, Whh,
                                                    accum, rowsum, nedges);

    // 4. finalize
    finalize_kernel<<<(n4 + 255) / 256, 256>>>(accum, rowsum, out, nrows);
}